// round 14
// baseline (speedup 1.0000x reference)
#include <cuda_runtime.h>
#include <cuda_fp16.h>
#include <cstdint>

// Problem constants
#define BATCH 64
#define TSEQ  1024
#define FDIM  512
#define IDIM  256
#define SDIM  128
#define MDIM  64
#define BT    (BATCH*TSEQ)           // 65536
#define UNFOLDS 6
#define NPAIR (SDIM/2)               // 64 j-pairs

// ---------------- device scratch (no device allocs allowed) ----------------
__device__ float  g_hidden[BT*IDIM];
__device__ float  g_gate  [BT*SDIM];
__device__ float  g_C     [BT*SDIM];
__device__ float  g_m     [BT*SDIM];
__device__ float  g_wns   [BT*SDIM];
__device__ float  g_wds   [BT*SDIM];
__device__ float2 g_sens_ab[IDIM*SDIM];   // (0.5*sig, -0.5*mu*sig)
__device__ float2 g_sens_wv[IDIM*SDIM];   // (0.5*w*m*erev, 0.5*w*m)
__device__ uint2  g_rec_ab2[NPAIR*SDIM];  // packed half2 (a_j0,a_j1),(b_j0,b_j1)
__device__ float  g_rec_wh [SDIM*SDIM];
__device__ float  g_rec_we [SDIM*SDIM];
__device__ float  g_cns[SDIM], g_cds[SDIM], g_cnr[SDIM], g_cdr[SDIM];

__device__ __forceinline__ float tanh_fast(float x) {
    float y;
    asm("tanh.approx.f32 %0, %1;" : "=f"(y) : "f"(x));
    return y;
}
__device__ __forceinline__ uint32_t tanh_h2(uint32_t x) {
    uint32_t y;
    asm("tanh.approx.f16x2 %0, %1;" : "=r"(y) : "r"(x));
    return y;
}
__device__ __forceinline__ uint32_t hfma2_u(uint32_t a, uint32_t b, uint32_t c) {
    uint32_t d;
    asm("fma.rn.f16x2 %0, %1, %2, %3;" : "=r"(d) : "r"(a), "r"(b), "r"(c));
    return d;
}
__device__ __forceinline__ float2 h2_to_f2(uint32_t h) {
    float lo, hi;
    asm("{.reg .f16 l, h;\n\t"
        " mov.b32 {l, h}, %2;\n\t"
        " cvt.f32.f16 %0, l;\n\t"
        " cvt.f32.f16 %1, h;}"
        : "=f"(lo), "=f"(hi) : "r"(h));
    return make_float2(lo, hi);
}
__device__ __forceinline__ uint32_t f2_to_h2(float lo, float hi) {
    uint32_t d;
    asm("cvt.rn.f16x2.f32 %0, %2, %1;" : "=r"(d) : "f"(lo), "f"(hi));
    return d;
}
__device__ __forceinline__ uint64_t pack_f2(float lo, float hi) {
    uint64_t r;
    asm("mov.b64 %0, {%1, %2};" : "=l"(r) : "f"(lo), "f"(hi));
    return r;
}
__device__ __forceinline__ float2 unpack_f2(uint64_t p) {
    float lo, hi;
    asm("mov.b64 {%0, %1}, %2;" : "=f"(lo), "=f"(hi) : "l"(p));
    return make_float2(lo, hi);
}
__device__ __forceinline__ uint64_t fma_f32x2(uint64_t a, uint64_t b, uint64_t c) {
    uint64_t d;
    asm("fma.rn.f32x2 %0, %1, %2, %3;" : "=l"(d) : "l"(a), "l"(b), "l"(c));
    return d;
}

// ---------------- generic fp32 GEMM: out = A[M,K] @ B[K,N] + bias ----------------
template<int KDIM, int NDIM, int MODE>
__global__ void __launch_bounds__(256) sgemm_kernel(
    const float* __restrict__ A, const float* __restrict__ B,
    const float* __restrict__ bias,
    float* __restrict__ out0, float* __restrict__ out1)
{
    constexpr int BM = 128, BN = 64, BK = 16;
    __shared__ float As[BK][BM];
    __shared__ float Bs[BK][BN];

    const int tid  = threadIdx.x;
    const int bx   = blockIdx.x;
    const int by   = blockIdx.y;
    const int tRow = tid >> 4;
    const int tCol = tid & 15;

    float acc[8][4];
#pragma unroll
    for (int i = 0; i < 8; i++)
#pragma unroll
        for (int j = 0; j < 4; j++) acc[i][j] = 0.f;

    const int aRow = tid >> 2;
    const int aC   = (tid & 3) * 4;
    const int bRow = tid >> 4;
    const int bC   = (tid & 15) * 4;

    for (int kt = 0; kt < KDIM; kt += BK) {
#pragma unroll
        for (int l = 0; l < 2; l++) {
            int r = aRow + l * 64;
            float4 v = *reinterpret_cast<const float4*>(
                &A[(size_t)(bx * BM + r) * KDIM + kt + aC]);
            As[aC + 0][r] = v.x; As[aC + 1][r] = v.y;
            As[aC + 2][r] = v.z; As[aC + 3][r] = v.w;
        }
        {
            float4 v = *reinterpret_cast<const float4*>(
                &B[(size_t)(kt + bRow) * NDIM + by * BN + bC]);
            *reinterpret_cast<float4*>(&Bs[bRow][bC]) = v;
        }
        __syncthreads();
#pragma unroll
        for (int k = 0; k < BK; k++) {
            float am[8], bn[4];
#pragma unroll
            for (int i = 0; i < 8; i++) am[i] = As[k][tRow * 8 + i];
#pragma unroll
            for (int j = 0; j < 4; j++) bn[j] = Bs[k][tCol * 4 + j];
#pragma unroll
            for (int i = 0; i < 8; i++)
#pragma unroll
                for (int j = 0; j < 4; j++)
                    acc[i][j] = fmaf(am[i], bn[j], acc[i][j]);
        }
        __syncthreads();
    }

#pragma unroll
    for (int i = 0; i < 8; i++) {
#pragma unroll
        for (int j = 0; j < 4; j++) {
            size_t row = (size_t)bx * BM + tRow * 8 + i;
            int col = by * BN + tCol * 4 + j;
            float v = acc[i][j] + bias[col];
            if (MODE == 0) {
                v = tanhf(v);
                if (col < IDIM) out0[row * IDIM + col] = v;
                else            out1[row * SDIM + (col - IDIM)] = v;
            } else if (MODE == 1) {
                out0[row * SDIM + col] = v;
            } else {
                out0[row * MDIM + col] = v;
            }
        }
    }
}

// ---------------- parameter transform + per-s constant sums ----------------
__global__ void param_prep(
    const float* __restrict__ w,   const float* __restrict__ sigma,
    const float* __restrict__ mu,  const float* __restrict__ erev,
    const float* __restrict__ mask,
    const float* __restrict__ sw_, const float* __restrict__ ssig,
    const float* __restrict__ smu, const float* __restrict__ serev,
    const float* __restrict__ smask)
{
    int s = threadIdx.x;  // 128 threads, 1 block
    float cns = 0.f, cds = 0.f;
    for (int i = 0; i < IDIM; i++) {
        int idx = i * SDIM + s;
        float a  = 0.5f * ssig[idx];
        g_sens_ab[idx] = make_float2(a, -smu[idx] * a);
        float wh = 0.5f * sw_[idx] * smask[idx];
        float we = wh * serev[idx];
        g_sens_wv[idx] = make_float2(we, wh);
        cns += we; cds += wh;
    }
    g_cns[s] = cns; g_cds[s] = cds;

    float cnr = 0.f, cdr = 0.f;
    for (int j = 0; j < SDIM; j++) {
        int idx = j * SDIM + s;
        float wh = 0.5f * w[idx] * mask[idx];
        float we = wh * erev[idx];
        g_rec_wh[idx] = wh; g_rec_we[idx] = we;
        cnr += we; cdr += wh;
    }
    g_cnr[s] = cnr; g_cdr[s] = cdr;

    // packed half2 recurrent (a,b) for j-pairs
    for (int p = 0; p < NPAIR; p++) {
        int j0 = 2 * p, j1 = 2 * p + 1;
        float a0 = 0.5f * sigma[j0 * SDIM + s];
        float a1 = 0.5f * sigma[j1 * SDIM + s];
        float b0 = -mu[j0 * SDIM + s] * a0;
        float b1 = -mu[j1 * SDIM + s] * a1;
        g_rec_ab2[p * SDIM + s] = make_uint2(f2_to_h2(a0, a1), f2_to_h2(b0, b1));
    }
}

// ---------------- softmax over T (axis=1) + sigmoid + multiply by C ----------------
__global__ void __launch_bounds__(512) softmax_m_kernel()
{
    __shared__ float red[512];
    const int b = blockIdx.x, tid = threadIdx.x;
    const int s = tid & 127, tc = tid >> 7;
    const float* g  = g_gate + (size_t)b * TSEQ * SDIM;
    const float* Cb = g_C    + (size_t)b * TSEQ * SDIM;
    float*       mb = g_m    + (size_t)b * TSEQ * SDIM;
    const int t0 = tc * 256;

    float mx = -1e30f;
    for (int t = t0; t < t0 + 256; t++) mx = fmaxf(mx, g[t * SDIM + s]);
    red[tid] = mx;
    __syncthreads();
    mx = fmaxf(fmaxf(red[s], red[128 + s]), fmaxf(red[256 + s], red[384 + s]));
    __syncthreads();

    float sum = 0.f;
    for (int t = t0; t < t0 + 256; t++) sum += __expf(g[t * SDIM + s] - mx);
    red[tid] = sum;
    __syncthreads();
    sum = red[s] + red[128 + s] + red[256 + s] + red[384 + s];
    float inv = __fdividef(1.0f, sum);

    for (int t = t0; t < t0 + 256; t++) {
        float e  = __expf(g[t * SDIM + s] - mx) * inv;
        float sg = fmaf(0.5f, tanh_fast(0.5f * e), 0.5f);  // sigmoid(e)
        mb[t * SDIM + s] = Cb[t * SDIM + s] * sg;
    }
}

// ---------------- sensory precompute ----------------
__global__ void __launch_bounds__(128) sensory_kernel(const float* __restrict__ hidden)
{
    __shared__ float h_sm[16][IDIM];
    const int tid = threadIdx.x;
    const size_t row0 = (size_t)blockIdx.x * 16;

    for (int idx = tid; idx < 16 * IDIM; idx += 128)
        h_sm[idx >> 8][idx & 255] = hidden[row0 * IDIM + idx];
    __syncthreads();

    const int s = tid;
    float an[16], ad[16];
#pragma unroll
    for (int r = 0; r < 16; r++) { an[r] = 0.f; ad[r] = 0.f; }

    for (int i = 0; i < IDIM; i++) {
        float2 ab = g_sens_ab[i * SDIM + s];
        float2 wv = g_sens_wv[i * SDIM + s];
#pragma unroll
        for (int r = 0; r < 16; r++) {
            float th = tanh_fast(fmaf(h_sm[r][i], ab.x, ab.y));
            an[r] = fmaf(wv.x, th, an[r]);
            ad[r] = fmaf(wv.y, th, ad[r]);
        }
    }
    const float cn = g_cns[s], cd = g_cds[s];
#pragma unroll
    for (int r = 0; r < 16; r++) {
        g_wns[(row0 + r) * SDIM + s] = an[r] + cn;
        g_wds[(row0 + r) * SDIM + s] = ad[r] + cd;
    }
}

// ---------------- sequential ODE scan (register-resident params) ----------------
// 1 CTA / batch, 512 threads, layout s=tid>>2, q=tid&3.
// Per-thread: 16 (a,b) half2 pairs in REGISTERS, fp32 weights packed f32x2 in
// registers, shfl-reduction over q, ping-pong v buffer -> ONE barrier/unfold.
__global__ void __launch_bounds__(512) scan_kernel(
    const float* __restrict__ ode_state,
    const float* __restrict__ gleak, const float* __restrict__ vleak,
    const float* __restrict__ cm,
    float* __restrict__ fused_out, float* __restrict__ final_out)
{
    __shared__ uint32_t vbuf[2][NPAIR];   // ping-pong packed half2 of v

    const int b = blockIdx.x, tid = threadIdx.x;
    const int s = tid >> 2, q = tid & 3;

    // register-resident parameters for this thread's 16 j-pairs
    uint2 abr[16];
    uint64_t wer2[16], whr2[16];
#pragma unroll
    for (int k = 0; k < 16; k++) {
        int p  = q * 16 + k;
        abr[k] = g_rec_ab2[p * SDIM + s];
        int j0 = 2 * p;
        wer2[k] = pack_f2(g_rec_we[j0 * SDIM + s], g_rec_we[(j0 + 1) * SDIM + s]);
        whr2[k] = pack_f2(g_rec_wh[j0 * SDIM + s], g_rec_wh[(j0 + 1) * SDIM + s]);
    }

    const float cmt = 6.0f * cm[s];
    const float gnc = gleak[s] * vleak[s] + g_cnr[s];   // glvl + crn
    const float glc = cmt + gleak[s] + g_cdr[s];        // cmt + gl + crd
    float v = ode_state[b * SDIM + s];
    if (q == 0)
        reinterpret_cast<__half*>(vbuf[0])[s] = __float2half_rn(v);
    __syncthreads();

    const float* wnsb = g_wns + (size_t)b * TSEQ * SDIM;
    const float* wdsb = g_wds + (size_t)b * TSEQ * SDIM;
    const float* mb   = g_m   + (size_t)b * TSEQ * SDIM;
    float*       fb   = fused_out + (size_t)b * TSEQ * SDIM;

    for (int t = 0; t < TSEQ; t++) {
        // all 4 lanes of a group load the same values (same L2 sectors)
        float wn = wnsb[t * SDIM + s];
        float wd = wdsb[t * SDIM + s];
        float mt = mb  [t * SDIM + s];
#pragma unroll 2
        for (int u = 0; u < UNFOLDS; u++) {
            const uint32_t* vr = vbuf[u & 1];
            uint64_t an = 0, ad = 0;
#pragma unroll
            for (int k = 0; k < 16; k++) {
                uint32_t vv = vr[q * 16 + k];                 // broadcast LDS
                uint32_t th = tanh_h2(hfma2_u(vv, abr[k].x, abr[k].y));
                float2   f  = h2_to_f2(th);
                uint64_t fp = pack_f2(f.x, f.y);
                an = fma_f32x2(wer2[k], fp, an);
                ad = fma_f32x2(whr2[k], fp, ad);
            }
            float2 a2 = unpack_f2(an);
            float2 d2 = unpack_f2(ad);
            float pn = a2.x + a2.y;
            float pd = d2.x + d2.y;
            pn += __shfl_xor_sync(0xFFFFFFFFu, pn, 1);
            pn += __shfl_xor_sync(0xFFFFFFFFu, pn, 2);
            pd += __shfl_xor_sync(0xFFFFFFFFu, pd, 1);
            pd += __shfl_xor_sync(0xFFFFFFFFu, pd, 2);
            if (q == 0) {
                float num = fmaf(cmt, v, gnc) + wn + pn;
                float den = glc + wd + pd;
                v = __fdividef(num, den + 1e-8f);
                reinterpret_cast<__half*>(vbuf[(u + 1) & 1])[s] = __float2half_rn(v);
            }
            __syncthreads();
        }
        if (q == 0) fb[t * SDIM + s] = v * mt;
    }
    if (q == 0) final_out[b * SDIM + s] = v;
}

// ---------------- launch ----------------
extern "C" void kernel_launch(void* const* d_in, const int* in_sizes, int n_in,
                              void* d_out, int out_size)
{
    const float* inputs   = (const float*)d_in[0];
    const float* ode_st   = (const float*)d_in[1];
    const float* W_in     = (const float*)d_in[2];
    const float* b_in     = (const float*)d_in[3];
    const float* W_c      = (const float*)d_in[4];
    const float* b_c      = (const float*)d_in[5];
    const float* W_out    = (const float*)d_in[6];
    const float* b_out    = (const float*)d_in[7];
    const float* gleak    = (const float*)d_in[8];
    const float* vleak    = (const float*)d_in[9];
    const float* cm       = (const float*)d_in[10];
    const float* w        = (const float*)d_in[11];
    const float* sigma    = (const float*)d_in[12];
    const float* mu       = (const float*)d_in[13];
    const float* sens_w   = (const float*)d_in[14];
    const float* sens_sig = (const float*)d_in[15];
    const float* sens_mu  = (const float*)d_in[16];
    const float* erev     = (const float*)d_in[17];
    const float* sens_er  = (const float*)d_in[18];
    const float* mask     = (const float*)d_in[19];
    const float* sens_msk = (const float*)d_in[20];
    (void)in_sizes; (void)n_in; (void)out_size;

    // d_out layout: [outputs BT*M][final_state B*S][fused BT*S]
    float* outputs = (float*)d_out;
    float* finalp  = outputs + (size_t)BT * MDIM;
    float* fusedp  = finalp  + (size_t)BATCH * SDIM;

    // Resolve TRUE device addresses of scratch symbols (host-side symbol decay
    // gives the host shadow address, which ATS silently accepts on GB300).
    float *p_hidden = nullptr, *p_gate = nullptr, *p_C = nullptr;
    cudaGetSymbolAddress((void**)&p_hidden, g_hidden);
    cudaGetSymbolAddress((void**)&p_gate,   g_gate);
    cudaGetSymbolAddress((void**)&p_C,      g_C);

    param_prep<<<1, 128>>>(w, sigma, mu, erev, mask,
                           sens_w, sens_sig, sens_mu, sens_er, sens_msk);
    sgemm_kernel<FDIM, IDIM + SDIM, 0><<<dim3(BT / 128, (IDIM + SDIM) / 64), 256>>>(
        inputs, W_in, b_in, p_hidden, p_gate);
    sgemm_kernel<IDIM, SDIM, 1><<<dim3(BT / 128, SDIM / 64), 256>>>(
        p_hidden, W_c, b_c, p_C, nullptr);
    softmax_m_kernel<<<BATCH, 512>>>();
    sensory_kernel<<<BT / 16, 128>>>(p_hidden);
    scan_kernel<<<BATCH, 512>>>(ode_st, gleak, vleak, cm, fusedp, finalp);
    sgemm_kernel<SDIM, MDIM, 2><<<dim3(BT / 128, 1), 256>>>(
        fusedp, W_out, b_out, outputs, nullptr);
}

// round 17
// speedup vs baseline: 1.4719x; 1.4719x over previous
#include <cuda_runtime.h>
#include <cuda_fp16.h>
#include <cstdint>

// Problem constants
#define BATCH 64
#define TSEQ  1024
#define FDIM  512
#define IDIM  256
#define SDIM  128
#define MDIM  64
#define BT    (BATCH*TSEQ)           // 65536
#define UNFOLDS 6
#define NPAIR (SDIM/2)               // 64 j-pairs

// ---------------- device scratch (no device allocs allowed) ----------------
__device__ float  g_hidden[BT*IDIM];
__device__ float  g_gate  [BT*SDIM];
__device__ float  g_C     [BT*SDIM];
__device__ float  g_m     [BT*SDIM];
__device__ float  g_wns   [BT*SDIM];
__device__ float  g_wds   [BT*SDIM];
__device__ float2 g_sens_ab[IDIM*SDIM];   // (0.5*sig, -0.5*mu*sig)
__device__ float2 g_sens_wv[IDIM*SDIM];   // (0.5*w*m*erev, 0.5*w*m)
__device__ uint2  g_rec_ab2[NPAIR*SDIM];  // packed half2 (a_j0,a_j1),(b_j0,b_j1)
__device__ float  g_rec_wh [SDIM*SDIM];
__device__ float  g_rec_we [SDIM*SDIM];
__device__ float  g_cns[SDIM], g_cds[SDIM], g_cnr[SDIM], g_cdr[SDIM];

__device__ __forceinline__ float tanh_fast(float x) {
    float y;
    asm("tanh.approx.f32 %0, %1;" : "=f"(y) : "f"(x));
    return y;
}
__device__ __forceinline__ uint32_t tanh_h2(uint32_t x) {
    uint32_t y;
    asm("tanh.approx.f16x2 %0, %1;" : "=r"(y) : "r"(x));
    return y;
}
__device__ __forceinline__ uint32_t hfma2_u(uint32_t a, uint32_t b, uint32_t c) {
    uint32_t d;
    asm("fma.rn.f16x2 %0, %1, %2, %3;" : "=r"(d) : "r"(a), "r"(b), "r"(c));
    return d;
}
__device__ __forceinline__ float2 h2_to_f2(uint32_t h) {
    float lo, hi;
    asm("{.reg .f16 l, h;\n\t"
        " mov.b32 {l, h}, %2;\n\t"
        " cvt.f32.f16 %0, l;\n\t"
        " cvt.f32.f16 %1, h;}"
        : "=f"(lo), "=f"(hi) : "r"(h));
    return make_float2(lo, hi);
}
__device__ __forceinline__ uint32_t f2_to_h2(float lo, float hi) {
    uint32_t d;
    asm("cvt.rn.f16x2.f32 %0, %2, %1;" : "=r"(d) : "f"(lo), "f"(hi));
    return d;
}

// ---------------- 128x128x8 fp32 GEMM, 8x8 micro-tile ----------------
// MODE 0: tanh epilogue, split store (by<2 -> hidden, by==2 -> gate)
// MODE 1: plain store, stride SDIM
template<int KDIM, int NDIM, int MODE>
__global__ void __launch_bounds__(256) sgemm2_kernel(
    const float* __restrict__ A, const float* __restrict__ B,
    const float* __restrict__ bias,
    float* __restrict__ out0, float* __restrict__ out1)
{
    constexpr int BM = 128, BN = 128, BK = 8;
    __shared__ float As[BK][BM];
    __shared__ float Bs[BK][BN];

    const int tid  = threadIdx.x;
    const int bx   = blockIdx.x;
    const int by   = blockIdx.y;
    const int tRow = tid >> 4;        // 0..15 -> rows tRow*8..+7
    const int tCol = tid & 15;        // 0..15 -> cols tCol*8..+7

    float acc[8][8];
#pragma unroll
    for (int i = 0; i < 8; i++)
#pragma unroll
        for (int j = 0; j < 8; j++) acc[i][j] = 0.f;

    const int aRow = tid >> 1;        // 0..127
    const int aK   = (tid & 1) * 4;   // 0 or 4
    const int bRow = tid >> 5;        // 0..7
    const int bC   = (tid & 31) * 4;  // 0..124

    for (int kt = 0; kt < KDIM; kt += BK) {
        {
            float4 av = *reinterpret_cast<const float4*>(
                &A[(size_t)(bx * BM + aRow) * KDIM + kt + aK]);
            As[aK + 0][aRow] = av.x; As[aK + 1][aRow] = av.y;
            As[aK + 2][aRow] = av.z; As[aK + 3][aRow] = av.w;
        }
        {
            float4 bv = *reinterpret_cast<const float4*>(
                &B[(size_t)(kt + bRow) * NDIM + by * BN + bC]);
            *reinterpret_cast<float4*>(&Bs[bRow][bC]) = bv;
        }
        __syncthreads();
#pragma unroll
        for (int k = 0; k < BK; k++) {
            float4 a0 = *reinterpret_cast<const float4*>(&As[k][tRow * 8]);
            float4 a1 = *reinterpret_cast<const float4*>(&As[k][tRow * 8 + 4]);
            float4 b0 = *reinterpret_cast<const float4*>(&Bs[k][tCol * 8]);
            float4 b1 = *reinterpret_cast<const float4*>(&Bs[k][tCol * 8 + 4]);
            float am[8] = {a0.x, a0.y, a0.z, a0.w, a1.x, a1.y, a1.z, a1.w};
            float bn[8] = {b0.x, b0.y, b0.z, b0.w, b1.x, b1.y, b1.z, b1.w};
#pragma unroll
            for (int i = 0; i < 8; i++)
#pragma unroll
                for (int j = 0; j < 8; j++)
                    acc[i][j] = fmaf(am[i], bn[j], acc[i][j]);
        }
        __syncthreads();
    }

    const int c0 = by * BN + tCol * 8;
#pragma unroll
    for (int i = 0; i < 8; i++) {
        size_t row = (size_t)bx * BM + tRow * 8 + i;
        float r[8];
#pragma unroll
        for (int j = 0; j < 8; j++) {
            r[j] = acc[i][j] + bias[c0 + j];
            if (MODE == 0) r[j] = tanhf(r[j]);
        }
        if (MODE == 0) {
            if (c0 < IDIM) {   // uniform per CTA (by<2)
                *reinterpret_cast<float4*>(&out0[row * IDIM + c0]) =
                    make_float4(r[0], r[1], r[2], r[3]);
                *reinterpret_cast<float4*>(&out0[row * IDIM + c0 + 4]) =
                    make_float4(r[4], r[5], r[6], r[7]);
            } else {
                int cg = c0 - IDIM;
                *reinterpret_cast<float4*>(&out1[row * SDIM + cg]) =
                    make_float4(r[0], r[1], r[2], r[3]);
                *reinterpret_cast<float4*>(&out1[row * SDIM + cg + 4]) =
                    make_float4(r[4], r[5], r[6], r[7]);
            }
        } else {
            *reinterpret_cast<float4*>(&out0[row * SDIM + c0]) =
                make_float4(r[0], r[1], r[2], r[3]);
            *reinterpret_cast<float4*>(&out0[row * SDIM + c0 + 4]) =
                make_float4(r[4], r[5], r[6], r[7]);
        }
    }
}

// ---------------- old 128x64 GEMM (kept for gemm_out, N=64) ----------------
template<int KDIM, int NDIM>
__global__ void __launch_bounds__(256) sgemm_out_kernel(
    const float* __restrict__ A, const float* __restrict__ B,
    const float* __restrict__ bias, float* __restrict__ out0)
{
    constexpr int BM = 128, BN = 64, BK = 16;
    __shared__ float As[BK][BM];
    __shared__ float Bs[BK][BN];

    const int tid  = threadIdx.x;
    const int bx   = blockIdx.x;
    const int tRow = tid >> 4;
    const int tCol = tid & 15;

    float acc[8][4];
#pragma unroll
    for (int i = 0; i < 8; i++)
#pragma unroll
        for (int j = 0; j < 4; j++) acc[i][j] = 0.f;

    const int aRow = tid >> 2;
    const int aC   = (tid & 3) * 4;
    const int bRow = tid >> 4;
    const int bC   = (tid & 15) * 4;

    for (int kt = 0; kt < KDIM; kt += BK) {
#pragma unroll
        for (int l = 0; l < 2; l++) {
            int r = aRow + l * 64;
            float4 v = *reinterpret_cast<const float4*>(
                &A[(size_t)(bx * BM + r) * KDIM + kt + aC]);
            As[aC + 0][r] = v.x; As[aC + 1][r] = v.y;
            As[aC + 2][r] = v.z; As[aC + 3][r] = v.w;
        }
        {
            float4 v = *reinterpret_cast<const float4*>(
                &B[(size_t)(kt + bRow) * NDIM + bC]);
            *reinterpret_cast<float4*>(&Bs[bRow][bC]) = v;
        }
        __syncthreads();
#pragma unroll
        for (int k = 0; k < BK; k++) {
            float am[8], bn[4];
#pragma unroll
            for (int i = 0; i < 8; i++) am[i] = As[k][tRow * 8 + i];
#pragma unroll
            for (int j = 0; j < 4; j++) bn[j] = Bs[k][tCol * 4 + j];
#pragma unroll
            for (int i = 0; i < 8; i++)
#pragma unroll
                for (int j = 0; j < 4; j++)
                    acc[i][j] = fmaf(am[i], bn[j], acc[i][j]);
        }
        __syncthreads();
    }

#pragma unroll
    for (int i = 0; i < 8; i++)
#pragma unroll
        for (int j = 0; j < 4; j++) {
            size_t row = (size_t)bx * BM + tRow * 8 + i;
            int col = tCol * 4 + j;
            out0[row * MDIM + col] = acc[i][j] + bias[col];
        }
}

// ---------------- parameter transform + per-s constant sums ----------------
__global__ void param_prep(
    const float* __restrict__ w,   const float* __restrict__ sigma,
    const float* __restrict__ mu,  const float* __restrict__ erev,
    const float* __restrict__ mask,
    const float* __restrict__ sw_, const float* __restrict__ ssig,
    const float* __restrict__ smu, const float* __restrict__ serev,
    const float* __restrict__ smask)
{
    int s = threadIdx.x;  // 128 threads, 1 block
    float cns = 0.f, cds = 0.f;
    for (int i = 0; i < IDIM; i++) {
        int idx = i * SDIM + s;
        float a  = 0.5f * ssig[idx];
        g_sens_ab[idx] = make_float2(a, -smu[idx] * a);
        float wh = 0.5f * sw_[idx] * smask[idx];
        float we = wh * serev[idx];
        g_sens_wv[idx] = make_float2(we, wh);
        cns += we; cds += wh;
    }
    g_cns[s] = cns; g_cds[s] = cds;

    float cnr = 0.f, cdr = 0.f;
    for (int j = 0; j < SDIM; j++) {
        int idx = j * SDIM + s;
        float wh = 0.5f * w[idx] * mask[idx];
        float we = wh * erev[idx];
        g_rec_wh[idx] = wh; g_rec_we[idx] = we;
        cnr += we; cdr += wh;
    }
    g_cnr[s] = cnr; g_cdr[s] = cdr;

    for (int p = 0; p < NPAIR; p++) {
        int j0 = 2 * p, j1 = 2 * p + 1;
        float a0 = 0.5f * sigma[j0 * SDIM + s];
        float a1 = 0.5f * sigma[j1 * SDIM + s];
        float b0 = -mu[j0 * SDIM + s] * a0;
        float b1 = -mu[j1 * SDIM + s] * a1;
        g_rec_ab2[p * SDIM + s] = make_uint2(f2_to_h2(a0, a1), f2_to_h2(b0, b1));
    }
}

// ---------------- softmax over T (axis=1) + sigmoid + multiply by C ----------------
__global__ void __launch_bounds__(512) softmax_m_kernel()
{
    __shared__ float red[512];
    const int b = blockIdx.x, tid = threadIdx.x;
    const int s = tid & 127, tc = tid >> 7;
    const float* g  = g_gate + (size_t)b * TSEQ * SDIM;
    const float* Cb = g_C    + (size_t)b * TSEQ * SDIM;
    float*       mb = g_m    + (size_t)b * TSEQ * SDIM;
    const int t0 = tc * 256;

    float mx = -1e30f;
    for (int t = t0; t < t0 + 256; t++) mx = fmaxf(mx, g[t * SDIM + s]);
    red[tid] = mx;
    __syncthreads();
    mx = fmaxf(fmaxf(red[s], red[128 + s]), fmaxf(red[256 + s], red[384 + s]));
    __syncthreads();

    float sum = 0.f;
    for (int t = t0; t < t0 + 256; t++) sum += __expf(g[t * SDIM + s] - mx);
    red[tid] = sum;
    __syncthreads();
    sum = red[s] + red[128 + s] + red[256 + s] + red[384 + s];
    float inv = __fdividef(1.0f, sum);

    for (int t = t0; t < t0 + 256; t++) {
        float e  = __expf(g[t * SDIM + s] - mx) * inv;
        float sg = fmaf(0.5f, tanh_fast(0.5f * e), 0.5f);  // sigmoid(e)
        mb[t * SDIM + s] = Cb[t * SDIM + s] * sg;
    }
}

// ---------------- sensory precompute ----------------
__global__ void __launch_bounds__(128) sensory_kernel(const float* __restrict__ hidden)
{
    __shared__ float h_sm[16][IDIM];
    const int tid = threadIdx.x;
    const size_t row0 = (size_t)blockIdx.x * 16;

    for (int idx = tid; idx < 16 * IDIM; idx += 128)
        h_sm[idx >> 8][idx & 255] = hidden[row0 * IDIM + idx];
    __syncthreads();

    const int s = tid;
    float an[16], ad[16];
#pragma unroll
    for (int r = 0; r < 16; r++) { an[r] = 0.f; ad[r] = 0.f; }

    for (int i = 0; i < IDIM; i++) {
        float2 ab = g_sens_ab[i * SDIM + s];
        float2 wv = g_sens_wv[i * SDIM + s];
#pragma unroll
        for (int r = 0; r < 16; r++) {
            float th = tanh_fast(fmaf(h_sm[r][i], ab.x, ab.y));
            an[r] = fmaf(wv.x, th, an[r]);
            ad[r] = fmaf(wv.y, th, ad[r]);
        }
    }
    const float cn = g_cns[s], cd = g_cds[s];
#pragma unroll
    for (int r = 0; r < 16; r++) {
        g_wns[(row0 + r) * SDIM + s] = an[r] + cn;
        g_wds[(row0 + r) * SDIM + s] = ad[r] + cd;
    }
}

// ---------------- sequential ODE scan (R13 structure + t+1 prefetch) ----------------
// 1 CTA / batch, 512 threads, s=tid&127, jg=tid>>7, 32 j's per thread.
__global__ void __launch_bounds__(512) scan_kernel(
    const float* __restrict__ ode_state,
    const float* __restrict__ gleak, const float* __restrict__ vleak,
    const float* __restrict__ cm,
    float* __restrict__ fused_out, float* __restrict__ final_out)
{
    __shared__ uint32_t v2_sm[NPAIR];   // packed half2 of v (pairs of j)
    __shared__ float red[1024];

    const int b = blockIdx.x, tid = threadIdx.x;
    const int s = tid & 127, jg = tid >> 7;

    // per-thread fp32 mixing weights for j = jg*32 .. jg*32+31  (64 regs)
    float whr[32], wer[32];
#pragma unroll
    for (int k = 0; k < 32; k++) {
        int j = jg * 32 + k;
        whr[k] = g_rec_wh[j * SDIM + s];
        wer[k] = g_rec_we[j * SDIM + s];
    }

    float cmt = 0.f, gl = 0.f, glvl = 0.f, crn = 0.f, crd = 0.f, v = 0.f;
    if (jg == 0) {
        cmt  = 6.0f * cm[s];
        gl   = gleak[s];
        glvl = gl * vleak[s];
        crn  = g_cnr[s];
        crd  = g_cdr[s];
        v    = ode_state[b * SDIM + s];
        reinterpret_cast<__half*>(v2_sm)[s] = __float2half_rn(v);
    }
    __syncthreads();

    const float* wnsb = g_wns + (size_t)b * TSEQ * SDIM;
    const float* wdsb = g_wds + (size_t)b * TSEQ * SDIM;
    const float* mb   = g_m   + (size_t)b * TSEQ * SDIM;
    float*       fb   = fused_out + (size_t)b * TSEQ * SDIM;

    const uint2* __restrict__ ab2 = g_rec_ab2;

    // prefetch registers for t-stream (hide L2 latency behind the unfolds)
    float wn_c = 0.f, wd_c = 0.f, mt_c = 0.f;
    if (jg == 0) {
        wn_c = wnsb[s];
        wd_c = wdsb[s];
        mt_c = mb[s];
    }

    for (int t = 0; t < TSEQ; t++) {
        float wn = wn_c, wd = wd_c, mt = mt_c;
        if (jg == 0 && t + 1 < TSEQ) {     // issue early; consumed next t
            wn_c = wnsb[(t + 1) * SDIM + s];
            wd_c = wdsb[(t + 1) * SDIM + s];
            mt_c = mb  [(t + 1) * SDIM + s];
        }
#pragma unroll 1
        for (int u = 0; u < UNFOLDS; u++) {
            float pn = 0.f, pd = 0.f;
#pragma unroll
            for (int k = 0; k < 16; k++) {
                int p = jg * 16 + k;                       // j pair (2p, 2p+1)
                uint32_t vv = v2_sm[p];                    // broadcast LDS
                uint2    ab = __ldg(&ab2[p * SDIM + s]);   // L1-resident params
                uint32_t th = tanh_h2(hfma2_u(vv, ab.x, ab.y));
                float2   f  = h2_to_f2(th);
                pn = fmaf(wer[2 * k], f.x, fmaf(wer[2 * k + 1], f.y, pn));
                pd = fmaf(whr[2 * k], f.x, fmaf(whr[2 * k + 1], f.y, pd));
            }
            red[tid]       = pn;
            red[512 + tid] = pd;
            __syncthreads();
            if (jg == 0) {
                float num = fmaf(cmt, v, glvl) + wn + crn
                          + red[s] + red[128 + s] + red[256 + s] + red[384 + s];
                float den = cmt + gl + wd + crd
                          + red[512 + s] + red[640 + s] + red[768 + s] + red[896 + s];
                v = __fdividef(num, den + 1e-8f);
                reinterpret_cast<__half*>(v2_sm)[s] = __float2half_rn(v);
            }
            __syncthreads();
        }
        if (jg == 0) fb[t * SDIM + s] = v * mt;
    }
    if (jg == 0) final_out[b * SDIM + s] = v;
}

// ---------------- launch ----------------
extern "C" void kernel_launch(void* const* d_in, const int* in_sizes, int n_in,
                              void* d_out, int out_size)
{
    const float* inputs   = (const float*)d_in[0];
    const float* ode_st   = (const float*)d_in[1];
    const float* W_in     = (const float*)d_in[2];
    const float* b_in     = (const float*)d_in[3];
    const float* W_c      = (const float*)d_in[4];
    const float* b_c      = (const float*)d_in[5];
    const float* W_out    = (const float*)d_in[6];
    const float* b_out    = (const float*)d_in[7];
    const float* gleak    = (const float*)d_in[8];
    const float* vleak    = (const float*)d_in[9];
    const float* cm       = (const float*)d_in[10];
    const float* w        = (const float*)d_in[11];
    const float* sigma    = (const float*)d_in[12];
    const float* mu       = (const float*)d_in[13];
    const float* sens_w   = (const float*)d_in[14];
    const float* sens_sig = (const float*)d_in[15];
    const float* sens_mu  = (const float*)d_in[16];
    const float* erev     = (const float*)d_in[17];
    const float* sens_er  = (const float*)d_in[18];
    const float* mask     = (const float*)d_in[19];
    const float* sens_msk = (const float*)d_in[20];
    (void)in_sizes; (void)n_in; (void)out_size;

    // d_out layout: [outputs BT*M][final_state B*S][fused BT*S]
    float* outputs = (float*)d_out;
    float* finalp  = outputs + (size_t)BT * MDIM;
    float* fusedp  = finalp  + (size_t)BATCH * SDIM;

    // Resolve TRUE device addresses of scratch symbols (host-side symbol decay
    // gives the host shadow address, which ATS silently accepts on GB300).
    float *p_hidden = nullptr, *p_gate = nullptr, *p_C = nullptr;
    cudaGetSymbolAddress((void**)&p_hidden, g_hidden);
    cudaGetSymbolAddress((void**)&p_gate,   g_gate);
    cudaGetSymbolAddress((void**)&p_C,      g_C);

    param_prep<<<1, 128>>>(w, sigma, mu, erev, mask,
                           sens_w, sens_sig, sens_mu, sens_er, sens_msk);
    // proj = tanh(X @ W_in + b) -> hidden/gate   (384 = 3 x 128 col tiles)
    sgemm2_kernel<FDIM, IDIM + SDIM, 0><<<dim3(BT / 128, 3), 256>>>(
        inputs, W_in, b_in, p_hidden, p_gate);
    // C = hidden @ W_c + b_c   (128 = 1 col tile)
    sgemm2_kernel<IDIM, SDIM, 1><<<dim3(BT / 128, 1), 256>>>(
        p_hidden, W_c, b_c, p_C, nullptr);
    softmax_m_kernel<<<BATCH, 512>>>();
    sensory_kernel<<<BT / 16, 128>>>(p_hidden);
    scan_kernel<<<BATCH, 512>>>(ode_st, gleak, vleak, cm, fusedp, finalp);
    sgemm_out_kernel<SDIM, MDIM><<<dim3(BT / 128, 1), 256>>>(
        fusedp, W_out, b_out, outputs);
}